// round 13
// baseline (speedup 1.0000x reference)
#include <cuda_runtime.h>
#include <cuda_fp16.h>
#include <cstdint>

#define H 128
#define MAXN 102400

// ---------------- scratch (device globals = sanctioned scratch) ----------------
__device__ float  g_agg[(size_t)MAXN * H];
__device__ __half g_h1[(size_t)MAXN * H];
__device__ __half g_h2[(size_t)MAXN * H];
__device__ uint4  g_wf1[16 * 8 * 32];  // K=256: s=16 (k16 steps), u2=8, lane=32 (64KB)
__device__ uint4  g_wf2[8 * 8 * 32];   // K=128 (32KB)
__device__ uint4  g_wf3[8 * 8 * 32];

__device__ __forceinline__ unsigned packh2(float lo, float hi) {
    __half2 h = __floats2half2_rn(lo, hi);
    return *reinterpret_cast<unsigned*>(&h);
}

__device__ __forceinline__ void mma_f16(float c[4], const unsigned a[4], const unsigned b[2]) {
    asm volatile(
        "mma.sync.aligned.m16n8k16.row.col.f32.f16.f16.f32 "
        "{%0,%1,%2,%3}, {%4,%5,%6,%7}, {%8,%9}, {%0,%1,%2,%3};"
        : "+f"(c[0]), "+f"(c[1]), "+f"(c[2]), "+f"(c[3])
        : "r"(a[0]), "r"(a[1]), "r"(a[2]), "r"(a[3]), "r"(b[0]), "r"(b[1]));
}

// Fast shifted softplus: ssp(y) = max(y,0) + (log2(1 + e^{-|y|}) - 1) * ln2
__device__ __forceinline__ float ssp_fast(float y) {
    const float LN2 = 0.69314718055994531f;
    float t = __expf(-fabsf(y));
    float l = __log2f(1.f + t);
    return fmaf(l - 1.f, LN2, fmaxf(y, 0.f));
}

// ---------------- merged weight pre-pack with K-permutation ----------------
// kappa (applied to BOTH A and B): frag-k {2t4,2t4+1,2t4+8,2t4+9} -> real-k {4t4..4t4+3}
__device__ __forceinline__ void wpack_one(const float* __restrict__ W,
                                          uint4* __restrict__ Wf, int idx) {
    int lane = idx & 31;
    int u2 = (idx >> 5) & 7;
    int s = idx >> 8;
    int n_e = u2 * 16 + (lane >> 2);
    int n_o = n_e + 8;
    int k0 = s * 16 + 4 * (lane & 3);
    uint4 v;
    v.x = packh2(W[(long long)k0 * H + n_e],       W[(long long)(k0 + 1) * H + n_e]);
    v.y = packh2(W[(long long)(k0 + 2) * H + n_e], W[(long long)(k0 + 3) * H + n_e]);
    v.z = packh2(W[(long long)k0 * H + n_o],       W[(long long)(k0 + 1) * H + n_o]);
    v.w = packh2(W[(long long)(k0 + 2) * H + n_o], W[(long long)(k0 + 3) * H + n_o]);
    Wf[idx] = v;
}

__global__ void wpack_all(const float* __restrict__ W1, uint4* __restrict__ Wf1,
                          const float* __restrict__ W2, uint4* __restrict__ Wf2,
                          const float* __restrict__ W3, uint4* __restrict__ Wf3) {
    int b = blockIdx.x;
    int t = threadIdx.x;
    if (b < 16)      wpack_one(W1, Wf1, b * 256 + t);
    else if (b < 24) wpack_one(W2, Wf2, (b - 16) * 256 + t);
    else             wpack_one(W3, Wf3, (b - 24) * 256 + t);
}

// ---------------- scatter: one warp per edge; ea streamed with L2 evict_first policy ----------------
__global__ void scatter_kernel(const float* __restrict__ ea,
                               const int* __restrict__ ei,
                               float* __restrict__ agg, int E) {
    long long idx = (long long)blockIdx.x * blockDim.x + threadIdx.x;
    int e = (int)(idx >> 5);
    if (e >= E) return;
    int c = ((int)idx & 31) << 2;
    int col = ei[E + e];  // edge_index[1][e] (int32)
    unsigned long long pol;
    asm("createpolicy.fractional.L2::evict_first.b64 %0, 1.0;" : "=l"(pol));
    float4 v;
    asm volatile("ld.global.nc.L2::cache_hint.v4.f32 {%0,%1,%2,%3}, [%4], %5;"
                 : "=f"(v.x), "=f"(v.y), "=f"(v.z), "=f"(v.w)
                 : "l"(ea + (long long)e * H + c), "l"(pol));
    float* dst = agg + (long long)col * H + c;
    asm volatile("red.global.add.v4.f32 [%0], {%1, %2, %3, %4};"
                 :: "l"(dst), "f"(v.x), "f"(v.y), "f"(v.z), "f"(v.w) : "memory");
}

// ---------------- fused layer: fp16 mma GEMM + bias + LN + ssp ----------------
// CTA = 128 rows x 128 cols, 8 warps = 4 row-groups (32 rows) x 2 col-halves (64 cols).
// Warp tile 32x64: B fragments reused across 2 m-tiles -> 1.5 B/elem through L1.
template <int S, bool CONCAT, bool HALF_IN, bool HALF_OUT>
__global__ __launch_bounds__(256, 2) void layer_mma(
    const void* __restrict__ a0src, const void* __restrict__ a1src,
    const uint4* __restrict__ Wf,
    const float* __restrict__ bias, const float* __restrict__ gamma,
    const float* __restrict__ beta, void* __restrict__ outv, int N) {
    __shared__ float2 sred[128][2];
    const int tid = threadIdx.x;
    const int w = tid >> 5;
    const int lane = tid & 31;
    const int t4 = lane & 3;
    const int wp = w >> 1;   // row group 0..3 (32 rows each)
    const int wh = w & 1;    // col half 0..1 (64 cols each)
    const int rbase = blockIdx.x * 128 + wp * 32 + (lane >> 2);

    // row offsets (elements) for the 4 row-slots: t*16 + h*8
    int rc[2][2];
#pragma unroll
    for (int t = 0; t < 2; ++t)
#pragma unroll
        for (int hh = 0; hh < 2; ++hh)
            rc[t][hh] = min(rbase + t * 16 + hh * 8, N - 1) * H;

    float acc[2][8][4];
#pragma unroll
    for (int t = 0; t < 2; ++t)
#pragma unroll
        for (int u = 0; u < 8; ++u)
#pragma unroll
            for (int j = 0; j < 4; ++j) acc[t][u][j] = 0.f;

#pragma unroll
    for (int s = 0; s < S; ++s) {
        const void* src;
        int kb;
        if (CONCAT && s >= 8) { src = a1src; kb = s * 16 - 128; }
        else                  { src = a0src; kb = s * 16; }
        unsigned a[2][4];
        if (HALF_IN) {
            const __half* hs = (const __half*)src;
#pragma unroll
            for (int t = 0; t < 2; ++t) {
                const uint2 q0 = __ldg((const uint2*)(hs + rc[t][0] + kb + 4 * t4));
                const uint2 q1 = __ldg((const uint2*)(hs + rc[t][1] + kb + 4 * t4));
                a[t][0] = q0.x; a[t][2] = q0.y;
                a[t][1] = q1.x; a[t][3] = q1.y;
            }
        } else {
            const float* fs = (const float*)src;
#pragma unroll
            for (int t = 0; t < 2; ++t) {
                const float4 f0 = __ldg((const float4*)(fs + rc[t][0] + kb + 4 * t4));
                const float4 f1 = __ldg((const float4*)(fs + rc[t][1] + kb + 4 * t4));
                a[t][0] = packh2(f0.x, f0.y); a[t][2] = packh2(f0.z, f0.w);
                a[t][1] = packh2(f1.x, f1.y); a[t][3] = packh2(f1.z, f1.w);
            }
        }
        const uint4* wf = Wf + (s * 8 + wh * 4) * 32 + lane;
#pragma unroll
        for (int j = 0; j < 4; ++j) {
            const uint4 bb = __ldg(wf + j * 32);
            unsigned b0[2] = {bb.x, bb.y};
            unsigned b1[2] = {bb.z, bb.w};
            mma_f16(acc[0][j * 2], a[0], b0);
            mma_f16(acc[0][j * 2 + 1], a[0], b1);
            mma_f16(acc[1][j * 2], a[1], b0);
            mma_f16(acc[1][j * 2 + 1], a[1], b1);
        }
    }

    // ---- epilogue: bias + LN (quad shuffle + 2-way cross-warp combine) + fast ssp ----
    const float inv = 1.f / (float)H;
    float s1[2][2] = {{0.f, 0.f}, {0.f, 0.f}};
    float s2[2][2] = {{0.f, 0.f}, {0.f, 0.f}};
#pragma unroll
    for (int j = 0; j < 4; ++j)
#pragma unroll
        for (int e = 0; e < 2; ++e) {
            int u = j * 2 + e;
            int cb = (wh * 4 + j) * 16 + e * 8 + t4 * 2;
            const float2 b2 = *reinterpret_cast<const float2*>(bias + cb);
#pragma unroll
            for (int t = 0; t < 2; ++t) {
                acc[t][u][0] += b2.x; acc[t][u][1] += b2.y;
                acc[t][u][2] += b2.x; acc[t][u][3] += b2.y;
                s1[t][0] += acc[t][u][0] + acc[t][u][1];
                s2[t][0] += acc[t][u][0] * acc[t][u][0] + acc[t][u][1] * acc[t][u][1];
                s1[t][1] += acc[t][u][2] + acc[t][u][3];
                s2[t][1] += acc[t][u][2] * acc[t][u][2] + acc[t][u][3] * acc[t][u][3];
            }
        }
#pragma unroll
    for (int off = 1; off <= 2; off <<= 1)
#pragma unroll
        for (int t = 0; t < 2; ++t)
#pragma unroll
            for (int hh = 0; hh < 2; ++hh) {
                s1[t][hh] += __shfl_xor_sync(0xffffffffu, s1[t][hh], off);
                s2[t][hh] += __shfl_xor_sync(0xffffffffu, s2[t][hh], off);
            }
    const int rl = wp * 32 + (lane >> 2);
    if (t4 == 0) {
#pragma unroll
        for (int t = 0; t < 2; ++t)
#pragma unroll
            for (int hh = 0; hh < 2; ++hh)
                sred[rl + t * 16 + hh * 8][wh] = make_float2(s1[t][hh], s2[t][hh]);
    }
    __syncthreads();
    float mu[2][2], rs[2][2];
#pragma unroll
    for (int t = 0; t < 2; ++t)
#pragma unroll
        for (int hh = 0; hh < 2; ++hh) {
            float2 p0 = sred[rl + t * 16 + hh * 8][0];
            float2 p1 = sred[rl + t * 16 + hh * 8][1];
            float m = (p0.x + p1.x) * inv;
            mu[t][hh] = m;
            rs[t][hh] = rsqrtf((p0.y + p1.y) * inv - m * m + 1e-5f);
        }

#pragma unroll
    for (int j = 0; j < 4; ++j)
#pragma unroll
        for (int e = 0; e < 2; ++e) {
            int u = j * 2 + e;
            int cb = (wh * 4 + j) * 16 + e * 8 + t4 * 2;
            const float2 gg = *reinterpret_cast<const float2*>(gamma + cb);
            const float2 be = *reinterpret_cast<const float2*>(beta + cb);
#pragma unroll
            for (int t = 0; t < 2; ++t)
#pragma unroll
                for (int hh = 0; hh < 2; ++hh) {
                    int r = rbase + t * 16 + hh * 8;
                    if (r < N) {
                        float y0 = (acc[t][u][hh * 2 + 0] - mu[t][hh]) * rs[t][hh] * gg.x + be.x;
                        float y1 = (acc[t][u][hh * 2 + 1] - mu[t][hh]) * rs[t][hh] * gg.y + be.y;
                        float o0 = ssp_fast(y0), o1 = ssp_fast(y1);
                        if (HALF_OUT)
                            *reinterpret_cast<__half2*>((__half*)outv + (long long)r * H + cb) =
                                __floats2half2_rn(o0, o1);
                        else
                            *reinterpret_cast<float2*>((float*)outv + (long long)r * H + cb) =
                                make_float2(o0, o1);
                    }
                }
        }
}

// ---------------- launch ----------------
extern "C" void kernel_launch(void* const* d_in, const int* in_sizes, int n_in,
                              void* d_out, int out_size) {
    const float* x   = (const float*)d_in[0];
    const int* ei    = (const int*)d_in[1];
    const float* ea  = (const float*)d_in[2];
    const float* W1  = (const float*)d_in[3];
    const float* b1  = (const float*)d_in[4];
    const float* g1  = (const float*)d_in[5];
    const float* be1 = (const float*)d_in[6];
    const float* W2  = (const float*)d_in[7];
    const float* b2  = (const float*)d_in[8];
    const float* g2  = (const float*)d_in[9];
    const float* be2 = (const float*)d_in[10];
    const float* W3  = (const float*)d_in[11];
    const float* b3  = (const float*)d_in[12];
    const float* g3  = (const float*)d_in[13];
    const float* be3 = (const float*)d_in[14];
    float* out = (float*)d_out;

    int N = in_sizes[0] / H;
    int E = in_sizes[1] / 2;

    float* agg;
    __half *h1, *h2;
    uint4 *wf1, *wf2, *wf3;
    cudaGetSymbolAddress((void**)&agg, g_agg);
    cudaGetSymbolAddress((void**)&h1, g_h1);
    cudaGetSymbolAddress((void**)&h2, g_h2);
    cudaGetSymbolAddress((void**)&wf1, g_wf1);
    cudaGetSymbolAddress((void**)&wf2, g_wf2);
    cudaGetSymbolAddress((void**)&wf3, g_wf3);

    cudaMemsetAsync(agg, 0, (size_t)N * H * sizeof(float));

    // single merged weight pre-pack launch
    wpack_all<<<32, 256>>>(W1, wf1, W2, wf2, W3, wf3);

    // scatter: 32 lanes per edge
    {
        long long tot = (long long)E * 32;
        int blocks = (int)((tot + 255) / 256);
        scatter_kernel<<<blocks, 256>>>(ea, ei, agg, E);
    }

    int gb = (N + 127) / 128;
    layer_mma<16, true,  false, true ><<<gb, 256>>>(x,  agg,     wf1, b1, g1, be1, h1,  N);
    layer_mma<8,  false, true,  true ><<<gb, 256>>>(h1, nullptr, wf2, b2, g2, be2, h2,  N);
    layer_mma<8,  false, true,  false><<<gb, 256>>>(h2, nullptr, wf3, b3, g3, be3, out, N);
}

// round 14
// speedup vs baseline: 1.0083x; 1.0083x over previous
#include <cuda_runtime.h>
#include <cuda_fp16.h>
#include <cstdint>

#define H 128
#define MAXN 102400

// ---------------- scratch (device globals = sanctioned scratch) ----------------
__device__ float  g_agg[(size_t)MAXN * H];
__device__ __half g_h1[(size_t)MAXN * H];
__device__ __half g_h2[(size_t)MAXN * H];
__device__ uint4  g_wf1[16 * 8 * 32];  // K=256: s=16 (k16 steps), u2=8, lane=32 (64KB)
__device__ uint4  g_wf2[8 * 8 * 32];   // K=128 (32KB)
__device__ uint4  g_wf3[8 * 8 * 32];

__device__ __forceinline__ unsigned packh2(float lo, float hi) {
    __half2 h = __floats2half2_rn(lo, hi);
    return *reinterpret_cast<unsigned*>(&h);
}

__device__ __forceinline__ void mma_f16(float c[4], const unsigned a[4], const unsigned b[2]) {
    asm volatile(
        "mma.sync.aligned.m16n8k16.row.col.f32.f16.f16.f32 "
        "{%0,%1,%2,%3}, {%4,%5,%6,%7}, {%8,%9}, {%0,%1,%2,%3};"
        : "+f"(c[0]), "+f"(c[1]), "+f"(c[2]), "+f"(c[3])
        : "r"(a[0]), "r"(a[1]), "r"(a[2]), "r"(a[3]), "r"(b[0]), "r"(b[1]));
}

// Fast shifted softplus: ssp(y) = max(y,0) + (log2(1 + e^{-|y|}) - 1) * ln2
__device__ __forceinline__ float ssp_fast(float y) {
    const float LN2 = 0.69314718055994531f;
    float t = __expf(-fabsf(y));
    float l = __log2f(1.f + t);
    return fmaf(l - 1.f, LN2, fmaxf(y, 0.f));
}

// ---------------- merged weight pre-pack with K-permutation ----------------
// kappa (applied to BOTH A and B): frag-k {2t4,2t4+1,2t4+8,2t4+9} -> real-k {4t4..4t4+3}
__device__ __forceinline__ void wpack_one(const float* __restrict__ W,
                                          uint4* __restrict__ Wf, int idx) {
    int lane = idx & 31;
    int u2 = (idx >> 5) & 7;
    int s = idx >> 8;
    int n_e = u2 * 16 + (lane >> 2);
    int n_o = n_e + 8;
    int k0 = s * 16 + 4 * (lane & 3);
    uint4 v;
    v.x = packh2(W[(long long)k0 * H + n_e],       W[(long long)(k0 + 1) * H + n_e]);
    v.y = packh2(W[(long long)(k0 + 2) * H + n_e], W[(long long)(k0 + 3) * H + n_e]);
    v.z = packh2(W[(long long)k0 * H + n_o],       W[(long long)(k0 + 1) * H + n_o]);
    v.w = packh2(W[(long long)(k0 + 2) * H + n_o], W[(long long)(k0 + 3) * H + n_o]);
    Wf[idx] = v;
}

__global__ void wpack_all(const float* __restrict__ W1, uint4* __restrict__ Wf1,
                          const float* __restrict__ W2, uint4* __restrict__ Wf2,
                          const float* __restrict__ W3, uint4* __restrict__ Wf3) {
    int b = blockIdx.x;
    int t = threadIdx.x;
    if (b < 16)      wpack_one(W1, Wf1, b * 256 + t);
    else if (b < 24) wpack_one(W2, Wf2, (b - 16) * 256 + t);
    else             wpack_one(W3, Wf3, (b - 24) * 256 + t);
}

// ---------------- scatter: one warp per edge; ea streamed with L2 evict_first policy ----------------
__global__ void scatter_kernel(const float* __restrict__ ea,
                               const int* __restrict__ ei,
                               float* __restrict__ agg, int E) {
    long long idx = (long long)blockIdx.x * blockDim.x + threadIdx.x;
    int e = (int)(idx >> 5);
    if (e >= E) return;
    int c = ((int)idx & 31) << 2;
    int col = ei[E + e];  // edge_index[1][e] (int32)
    unsigned long long pol;
    asm("createpolicy.fractional.L2::evict_first.b64 %0, 1.0;" : "=l"(pol));
    float4 v;
    asm volatile("ld.global.nc.L2::cache_hint.v4.f32 {%0,%1,%2,%3}, [%4], %5;"
                 : "=f"(v.x), "=f"(v.y), "=f"(v.z), "=f"(v.w)
                 : "l"(ea + (long long)e * H + c), "l"(pol));
    float* dst = agg + (long long)col * H + c;
    asm volatile("red.global.add.v4.f32 [%0], {%1, %2, %3, %4};"
                 :: "l"(dst), "f"(v.x), "f"(v.y), "f"(v.z), "f"(v.w) : "memory");
}

// ---------------- fused layer: fp16 mma GEMM + bias + LN + ssp ----------------
// CTA = 128 rows x 128 cols, 8 warps = 4 row-groups (32 rows) x 2 col-halves (64 cols).
// Warp tile 32x64: B fragments reused across 2 m-tiles -> 1.5 B/elem through L1.
template <int S, bool CONCAT, bool HALF_IN, bool HALF_OUT>
__global__ __launch_bounds__(256, 2) void layer_mma(
    const void* __restrict__ a0src, const void* __restrict__ a1src,
    const uint4* __restrict__ Wf,
    const float* __restrict__ bias, const float* __restrict__ gamma,
    const float* __restrict__ beta, void* __restrict__ outv, int N) {
    __shared__ float2 sred[128][2];
    const int tid = threadIdx.x;
    const int w = tid >> 5;
    const int lane = tid & 31;
    const int t4 = lane & 3;
    const int wp = w >> 1;   // row group 0..3 (32 rows each)
    const int wh = w & 1;    // col half 0..1 (64 cols each)
    const int rbase = blockIdx.x * 128 + wp * 32 + (lane >> 2);

    // row offsets (elements) for the 4 row-slots: t*16 + h*8
    int rc[2][2];
#pragma unroll
    for (int t = 0; t < 2; ++t)
#pragma unroll
        for (int hh = 0; hh < 2; ++hh)
            rc[t][hh] = min(rbase + t * 16 + hh * 8, N - 1) * H;

    float acc[2][8][4];
#pragma unroll
    for (int t = 0; t < 2; ++t)
#pragma unroll
        for (int u = 0; u < 8; ++u)
#pragma unroll
            for (int j = 0; j < 4; ++j) acc[t][u][j] = 0.f;

#pragma unroll
    for (int s = 0; s < S; ++s) {
        const void* src;
        int kb;
        if (CONCAT && s >= 8) { src = a1src; kb = s * 16 - 128; }
        else                  { src = a0src; kb = s * 16; }
        unsigned a[2][4];
        if (HALF_IN) {
            const __half* hs = (const __half*)src;
#pragma unroll
            for (int t = 0; t < 2; ++t) {
                const uint2 q0 = __ldg((const uint2*)(hs + rc[t][0] + kb + 4 * t4));
                const uint2 q1 = __ldg((const uint2*)(hs + rc[t][1] + kb + 4 * t4));
                a[t][0] = q0.x; a[t][2] = q0.y;
                a[t][1] = q1.x; a[t][3] = q1.y;
            }
        } else {
            const float* fs = (const float*)src;
#pragma unroll
            for (int t = 0; t < 2; ++t) {
                const float4 f0 = __ldg((const float4*)(fs + rc[t][0] + kb + 4 * t4));
                const float4 f1 = __ldg((const float4*)(fs + rc[t][1] + kb + 4 * t4));
                a[t][0] = packh2(f0.x, f0.y); a[t][2] = packh2(f0.z, f0.w);
                a[t][1] = packh2(f1.x, f1.y); a[t][3] = packh2(f1.z, f1.w);
            }
        }
        const uint4* wf = Wf + (s * 8 + wh * 4) * 32 + lane;
#pragma unroll
        for (int j = 0; j < 4; ++j) {
            const uint4 bb = __ldg(wf + j * 32);
            unsigned b0[2] = {bb.x, bb.y};
            unsigned b1[2] = {bb.z, bb.w};
            mma_f16(acc[0][j * 2], a[0], b0);
            mma_f16(acc[0][j * 2 + 1], a[0], b1);
            mma_f16(acc[1][j * 2], a[1], b0);
            mma_f16(acc[1][j * 2 + 1], a[1], b1);
        }
    }

    // ---- epilogue: bias + LN (quad shuffle + 2-way cross-warp combine) + fast ssp ----
    const float inv = 1.f / (float)H;
    float s1[2][2] = {{0.f, 0.f}, {0.f, 0.f}};
    float s2[2][2] = {{0.f, 0.f}, {0.f, 0.f}};
#pragma unroll
    for (int j = 0; j < 4; ++j)
#pragma unroll
        for (int e = 0; e < 2; ++e) {
            int u = j * 2 + e;
            int cb = (wh * 4 + j) * 16 + e * 8 + t4 * 2;
            const float2 b2 = *reinterpret_cast<const float2*>(bias + cb);
#pragma unroll
            for (int t = 0; t < 2; ++t) {
                acc[t][u][0] += b2.x; acc[t][u][1] += b2.y;
                acc[t][u][2] += b2.x; acc[t][u][3] += b2.y;
                s1[t][0] += acc[t][u][0] + acc[t][u][1];
                s2[t][0] += acc[t][u][0] * acc[t][u][0] + acc[t][u][1] * acc[t][u][1];
                s1[t][1] += acc[t][u][2] + acc[t][u][3];
                s2[t][1] += acc[t][u][2] * acc[t][u][2] + acc[t][u][3] * acc[t][u][3];
            }
        }
#pragma unroll
    for (int off = 1; off <= 2; off <<= 1)
#pragma unroll
        for (int t = 0; t < 2; ++t)
#pragma unroll
            for (int hh = 0; hh < 2; ++hh) {
                s1[t][hh] += __shfl_xor_sync(0xffffffffu, s1[t][hh], off);
                s2[t][hh] += __shfl_xor_sync(0xffffffffu, s2[t][hh], off);
            }
    const int rl = wp * 32 + (lane >> 2);
    if (t4 == 0) {
#pragma unroll
        for (int t = 0; t < 2; ++t)
#pragma unroll
            for (int hh = 0; hh < 2; ++hh)
                sred[rl + t * 16 + hh * 8][wh] = make_float2(s1[t][hh], s2[t][hh]);
    }
    __syncthreads();
    float mu[2][2], rs[2][2];
#pragma unroll
    for (int t = 0; t < 2; ++t)
#pragma unroll
        for (int hh = 0; hh < 2; ++hh) {
            float2 p0 = sred[rl + t * 16 + hh * 8][0];
            float2 p1 = sred[rl + t * 16 + hh * 8][1];
            float m = (p0.x + p1.x) * inv;
            mu[t][hh] = m;
            rs[t][hh] = rsqrtf((p0.y + p1.y) * inv - m * m + 1e-5f);
        }

#pragma unroll
    for (int j = 0; j < 4; ++j)
#pragma unroll
        for (int e = 0; e < 2; ++e) {
            int u = j * 2 + e;
            int cb = (wh * 4 + j) * 16 + e * 8 + t4 * 2;
            const float2 gg = *reinterpret_cast<const float2*>(gamma + cb);
            const float2 be = *reinterpret_cast<const float2*>(beta + cb);
#pragma unroll
            for (int t = 0; t < 2; ++t)
#pragma unroll
                for (int hh = 0; hh < 2; ++hh) {
                    int r = rbase + t * 16 + hh * 8;
                    if (r < N) {
                        float y0 = (acc[t][u][hh * 2 + 0] - mu[t][hh]) * rs[t][hh] * gg.x + be.x;
                        float y1 = (acc[t][u][hh * 2 + 1] - mu[t][hh]) * rs[t][hh] * gg.y + be.y;
                        float o0 = ssp_fast(y0), o1 = ssp_fast(y1);
                        if (HALF_OUT)
                            *reinterpret_cast<__half2*>((__half*)outv + (long long)r * H + cb) =
                                __floats2half2_rn(o0, o1);
                        else
                            *reinterpret_cast<float2*>((float*)outv + (long long)r * H + cb) =
                                make_float2(o0, o1);
                    }
                }
        }
}

// ---------------- launch ----------------
extern "C" void kernel_launch(void* const* d_in, const int* in_sizes, int n_in,
                              void* d_out, int out_size) {
    const float* x   = (const float*)d_in[0];
    const int* ei    = (const int*)d_in[1];
    const float* ea  = (const float*)d_in[2];
    const float* W1  = (const float*)d_in[3];
    const float* b1  = (const float*)d_in[4];
    const float* g1  = (const float*)d_in[5];
    const float* be1 = (const float*)d_in[6];
    const float* W2  = (const float*)d_in[7];
    const float* b2  = (const float*)d_in[8];
    const float* g2  = (const float*)d_in[9];
    const float* be2 = (const float*)d_in[10];
    const float* W3  = (const float*)d_in[11];
    const float* b3  = (const float*)d_in[12];
    const float* g3  = (const float*)d_in[13];
    const float* be3 = (const float*)d_in[14];
    float* out = (float*)d_out;

    int N = in_sizes[0] / H;
    int E = in_sizes[1] / 2;

    float* agg;
    __half *h1, *h2;
    uint4 *wf1, *wf2, *wf3;
    cudaGetSymbolAddress((void**)&agg, g_agg);
    cudaGetSymbolAddress((void**)&h1, g_h1);
    cudaGetSymbolAddress((void**)&h2, g_h2);
    cudaGetSymbolAddress((void**)&wf1, g_wf1);
    cudaGetSymbolAddress((void**)&wf2, g_wf2);
    cudaGetSymbolAddress((void**)&wf3, g_wf3);

    cudaMemsetAsync(agg, 0, (size_t)N * H * sizeof(float));

    // single merged weight pre-pack launch
    wpack_all<<<32, 256>>>(W1, wf1, W2, wf2, W3, wf3);

    // scatter: 32 lanes per edge
    {
        long long tot = (long long)E * 32;
        int blocks = (int)((tot + 255) / 256);
        scatter_kernel<<<blocks, 256>>>(ea, ei, agg, E);
    }

    int gb = (N + 127) / 128;
    layer_mma<16, true,  false, true ><<<gb, 256>>>(x,  agg,     wf1, b1, g1, be1, h1,  N);
    layer_mma<8,  false, true,  true ><<<gb, 256>>>(h1, nullptr, wf2, b2, g2, be2, h2,  N);
    layer_mma<8,  false, true,  false><<<gb, 256>>>(h2, nullptr, wf3, b3, g3, be3, out, N);
}

// round 15
// speedup vs baseline: 1.0098x; 1.0014x over previous
#include <cuda_runtime.h>
#include <cuda_fp16.h>
#include <cstdint>

#define H 128
#define MAXN 102400

// ---------------- scratch (device globals = sanctioned scratch) ----------------
__device__ float  g_agg[(size_t)MAXN * H];
__device__ __half g_h1[(size_t)MAXN * H];
__device__ __half g_h2[(size_t)MAXN * H];
__device__ uint4  g_wf1[16 * 8 * 32];  // K=256: s=16 (k16 steps), u2=8, lane=32 (64KB)
__device__ uint4  g_wf2[8 * 8 * 32];   // K=128 (32KB)
__device__ uint4  g_wf3[8 * 8 * 32];

__device__ __forceinline__ unsigned packh2(float lo, float hi) {
    __half2 h = __floats2half2_rn(lo, hi);
    return *reinterpret_cast<unsigned*>(&h);
}

__device__ __forceinline__ void mma_f16(float c[4], const unsigned a[4], const unsigned b[2]) {
    asm volatile(
        "mma.sync.aligned.m16n8k16.row.col.f32.f16.f16.f32 "
        "{%0,%1,%2,%3}, {%4,%5,%6,%7}, {%8,%9}, {%0,%1,%2,%3};"
        : "+f"(c[0]), "+f"(c[1]), "+f"(c[2]), "+f"(c[3])
        : "r"(a[0]), "r"(a[1]), "r"(a[2]), "r"(a[3]), "r"(b[0]), "r"(b[1]));
}

// Fast shifted softplus: ssp(y) = max(y,0) + (log2(1 + e^{-|y|}) - 1) * ln2
__device__ __forceinline__ float ssp_fast(float y) {
    const float LN2 = 0.69314718055994531f;
    float t = __expf(-fabsf(y));
    float l = __log2f(1.f + t);
    return fmaf(l - 1.f, LN2, fmaxf(y, 0.f));
}

// ---------------- merged weight pre-pack with K-permutation ----------------
// kappa (applied to BOTH A and B): frag-k {2t4,2t4+1,2t4+8,2t4+9} -> real-k {4t4..4t4+3}
__device__ __forceinline__ void wpack_one(const float* __restrict__ W,
                                          uint4* __restrict__ Wf, int idx) {
    int lane = idx & 31;
    int u2 = (idx >> 5) & 7;
    int s = idx >> 8;
    int n_e = u2 * 16 + (lane >> 2);
    int n_o = n_e + 8;
    int k0 = s * 16 + 4 * (lane & 3);
    uint4 v;
    v.x = packh2(W[(long long)k0 * H + n_e],       W[(long long)(k0 + 1) * H + n_e]);
    v.y = packh2(W[(long long)(k0 + 2) * H + n_e], W[(long long)(k0 + 3) * H + n_e]);
    v.z = packh2(W[(long long)k0 * H + n_o],       W[(long long)(k0 + 1) * H + n_o]);
    v.w = packh2(W[(long long)(k0 + 2) * H + n_o], W[(long long)(k0 + 3) * H + n_o]);
    Wf[idx] = v;
}

__global__ void wpack_all(const float* __restrict__ W1, uint4* __restrict__ Wf1,
                          const float* __restrict__ W2, uint4* __restrict__ Wf2,
                          const float* __restrict__ W3, uint4* __restrict__ Wf3) {
    int b = blockIdx.x;
    int t = threadIdx.x;
    if (b < 16)      wpack_one(W1, Wf1, b * 256 + t);
    else if (b < 24) wpack_one(W2, Wf2, (b - 16) * 256 + t);
    else             wpack_one(W3, Wf3, (b - 24) * 256 + t);
}

// ---------------- scatter: one warp per edge; ea streamed with L2 evict_first policy ----------------
__global__ void scatter_kernel(const float* __restrict__ ea,
                               const int* __restrict__ ei,
                               float* __restrict__ agg, int E) {
    long long idx = (long long)blockIdx.x * blockDim.x + threadIdx.x;
    int e = (int)(idx >> 5);
    if (e >= E) return;
    int c = ((int)idx & 31) << 2;
    int col = ei[E + e];  // edge_index[1][e] (int32)
    unsigned long long pol;
    asm("createpolicy.fractional.L2::evict_first.b64 %0, 1.0;" : "=l"(pol));
    float4 v;
    asm volatile("ld.global.nc.L2::cache_hint.v4.f32 {%0,%1,%2,%3}, [%4], %5;"
                 : "=f"(v.x), "=f"(v.y), "=f"(v.z), "=f"(v.w)
                 : "l"(ea + (long long)e * H + c), "l"(pol));
    float* dst = agg + (long long)col * H + c;
    asm volatile("red.global.add.v4.f32 [%0], {%1, %2, %3, %4};"
                 :: "l"(dst), "f"(v.x), "f"(v.y), "f"(v.z), "f"(v.w) : "memory");
}

// ---------------- fused layer: fp16 mma GEMM + bias + LN + ssp ----------------
// CTA = 128 rows x 128 cols, 8 warps = 4 row-groups (32 rows) x 2 col-halves (64 cols).
// Warp tile 32x64: B fragments reused across 2 m-tiles -> 1.5 B/elem through L1.
template <int S, bool CONCAT, bool HALF_IN, bool HALF_OUT>
__global__ __launch_bounds__(256, 2) void layer_mma(
    const void* __restrict__ a0src, const void* __restrict__ a1src,
    const uint4* __restrict__ Wf,
    const float* __restrict__ bias, const float* __restrict__ gamma,
    const float* __restrict__ beta, void* __restrict__ outv, int N) {
    __shared__ float2 sred[128][2];
    const int tid = threadIdx.x;
    const int w = tid >> 5;
    const int lane = tid & 31;
    const int t4 = lane & 3;
    const int wp = w >> 1;   // row group 0..3 (32 rows each)
    const int wh = w & 1;    // col half 0..1 (64 cols each)
    const int rbase = blockIdx.x * 128 + wp * 32 + (lane >> 2);

    // row offsets (elements) for the 4 row-slots: t*16 + h*8
    int rc[2][2];
#pragma unroll
    for (int t = 0; t < 2; ++t)
#pragma unroll
        for (int hh = 0; hh < 2; ++hh)
            rc[t][hh] = min(rbase + t * 16 + hh * 8, N - 1) * H;

    float acc[2][8][4];
#pragma unroll
    for (int t = 0; t < 2; ++t)
#pragma unroll
        for (int u = 0; u < 8; ++u)
#pragma unroll
            for (int j = 0; j < 4; ++j) acc[t][u][j] = 0.f;

#pragma unroll
    for (int s = 0; s < S; ++s) {
        const void* src;
        int kb;
        if (CONCAT && s >= 8) { src = a1src; kb = s * 16 - 128; }
        else                  { src = a0src; kb = s * 16; }
        unsigned a[2][4];
        if (HALF_IN) {
            const __half* hs = (const __half*)src;
#pragma unroll
            for (int t = 0; t < 2; ++t) {
                const uint2 q0 = __ldg((const uint2*)(hs + rc[t][0] + kb + 4 * t4));
                const uint2 q1 = __ldg((const uint2*)(hs + rc[t][1] + kb + 4 * t4));
                a[t][0] = q0.x; a[t][2] = q0.y;
                a[t][1] = q1.x; a[t][3] = q1.y;
            }
        } else {
            const float* fs = (const float*)src;
#pragma unroll
            for (int t = 0; t < 2; ++t) {
                const float4 f0 = __ldg((const float4*)(fs + rc[t][0] + kb + 4 * t4));
                const float4 f1 = __ldg((const float4*)(fs + rc[t][1] + kb + 4 * t4));
                a[t][0] = packh2(f0.x, f0.y); a[t][2] = packh2(f0.z, f0.w);
                a[t][1] = packh2(f1.x, f1.y); a[t][3] = packh2(f1.z, f1.w);
            }
        }
        const uint4* wf = Wf + (s * 8 + wh * 4) * 32 + lane;
#pragma unroll
        for (int j = 0; j < 4; ++j) {
            const uint4 bb = __ldg(wf + j * 32);
            unsigned b0[2] = {bb.x, bb.y};
            unsigned b1[2] = {bb.z, bb.w};
            mma_f16(acc[0][j * 2], a[0], b0);
            mma_f16(acc[0][j * 2 + 1], a[0], b1);
            mma_f16(acc[1][j * 2], a[1], b0);
            mma_f16(acc[1][j * 2 + 1], a[1], b1);
        }
    }

    // ---- epilogue: bias + LN (quad shuffle + 2-way cross-warp combine) + fast ssp ----
    const float inv = 1.f / (float)H;
    float s1[2][2] = {{0.f, 0.f}, {0.f, 0.f}};
    float s2[2][2] = {{0.f, 0.f}, {0.f, 0.f}};
#pragma unroll
    for (int j = 0; j < 4; ++j)
#pragma unroll
        for (int e = 0; e < 2; ++e) {
            int u = j * 2 + e;
            int cb = (wh * 4 + j) * 16 + e * 8 + t4 * 2;
            const float2 b2 = *reinterpret_cast<const float2*>(bias + cb);
#pragma unroll
            for (int t = 0; t < 2; ++t) {
                acc[t][u][0] += b2.x; acc[t][u][1] += b2.y;
                acc[t][u][2] += b2.x; acc[t][u][3] += b2.y;
                s1[t][0] += acc[t][u][0] + acc[t][u][1];
                s2[t][0] += acc[t][u][0] * acc[t][u][0] + acc[t][u][1] * acc[t][u][1];
                s1[t][1] += acc[t][u][2] + acc[t][u][3];
                s2[t][1] += acc[t][u][2] * acc[t][u][2] + acc[t][u][3] * acc[t][u][3];
            }
        }
#pragma unroll
    for (int off = 1; off <= 2; off <<= 1)
#pragma unroll
        for (int t = 0; t < 2; ++t)
#pragma unroll
            for (int hh = 0; hh < 2; ++hh) {
                s1[t][hh] += __shfl_xor_sync(0xffffffffu, s1[t][hh], off);
                s2[t][hh] += __shfl_xor_sync(0xffffffffu, s2[t][hh], off);
            }
    const int rl = wp * 32 + (lane >> 2);
    if (t4 == 0) {
#pragma unroll
        for (int t = 0; t < 2; ++t)
#pragma unroll
            for (int hh = 0; hh < 2; ++hh)
                sred[rl + t * 16 + hh * 8][wh] = make_float2(s1[t][hh], s2[t][hh]);
    }
    __syncthreads();
    float mu[2][2], rs[2][2];
#pragma unroll
    for (int t = 0; t < 2; ++t)
#pragma unroll
        for (int hh = 0; hh < 2; ++hh) {
            float2 p0 = sred[rl + t * 16 + hh * 8][0];
            float2 p1 = sred[rl + t * 16 + hh * 8][1];
            float m = (p0.x + p1.x) * inv;
            mu[t][hh] = m;
            rs[t][hh] = rsqrtf((p0.y + p1.y) * inv - m * m + 1e-5f);
        }

#pragma unroll
    for (int j = 0; j < 4; ++j)
#pragma unroll
        for (int e = 0; e < 2; ++e) {
            int u = j * 2 + e;
            int cb = (wh * 4 + j) * 16 + e * 8 + t4 * 2;
            const float2 gg = *reinterpret_cast<const float2*>(gamma + cb);
            const float2 be = *reinterpret_cast<const float2*>(beta + cb);
#pragma unroll
            for (int t = 0; t < 2; ++t)
#pragma unroll
                for (int hh = 0; hh < 2; ++hh) {
                    int r = rbase + t * 16 + hh * 8;
                    if (r < N) {
                        float y0 = (acc[t][u][hh * 2 + 0] - mu[t][hh]) * rs[t][hh] * gg.x + be.x;
                        float y1 = (acc[t][u][hh * 2 + 1] - mu[t][hh]) * rs[t][hh] * gg.y + be.y;
                        float o0 = ssp_fast(y0), o1 = ssp_fast(y1);
                        if (HALF_OUT)
                            *reinterpret_cast<__half2*>((__half*)outv + (long long)r * H + cb) =
                                __floats2half2_rn(o0, o1);
                        else
                            *reinterpret_cast<float2*>((float*)outv + (long long)r * H + cb) =
                                make_float2(o0, o1);
                    }
                }
        }
}

// ---------------- launch ----------------
extern "C" void kernel_launch(void* const* d_in, const int* in_sizes, int n_in,
                              void* d_out, int out_size) {
    const float* x   = (const float*)d_in[0];
    const int* ei    = (const int*)d_in[1];
    const float* ea  = (const float*)d_in[2];
    const float* W1  = (const float*)d_in[3];
    const float* b1  = (const float*)d_in[4];
    const float* g1  = (const float*)d_in[5];
    const float* be1 = (const float*)d_in[6];
    const float* W2  = (const float*)d_in[7];
    const float* b2  = (const float*)d_in[8];
    const float* g2  = (const float*)d_in[9];
    const float* be2 = (const float*)d_in[10];
    const float* W3  = (const float*)d_in[11];
    const float* b3  = (const float*)d_in[12];
    const float* g3  = (const float*)d_in[13];
    const float* be3 = (const float*)d_in[14];
    float* out = (float*)d_out;

    int N = in_sizes[0] / H;
    int E = in_sizes[1] / 2;

    float* agg;
    __half *h1, *h2;
    uint4 *wf1, *wf2, *wf3;
    cudaGetSymbolAddress((void**)&agg, g_agg);
    cudaGetSymbolAddress((void**)&h1, g_h1);
    cudaGetSymbolAddress((void**)&h2, g_h2);
    cudaGetSymbolAddress((void**)&wf1, g_wf1);
    cudaGetSymbolAddress((void**)&wf2, g_wf2);
    cudaGetSymbolAddress((void**)&wf3, g_wf3);

    cudaMemsetAsync(agg, 0, (size_t)N * H * sizeof(float));

    // single merged weight pre-pack launch
    wpack_all<<<32, 256>>>(W1, wf1, W2, wf2, W3, wf3);

    // scatter: 32 lanes per edge
    {
        long long tot = (long long)E * 32;
        int blocks = (int)((tot + 255) / 256);
        scatter_kernel<<<blocks, 256>>>(ea, ei, agg, E);
    }

    int gb = (N + 127) / 128;
    layer_mma<16, true,  false, true ><<<gb, 256>>>(x,  agg,     wf1, b1, g1, be1, h1,  N);
    layer_mma<8,  false, true,  true ><<<gb, 256>>>(h1, nullptr, wf2, b2, g2, be2, h2,  N);
    layer_mma<8,  false, true,  false><<<gb, 256>>>(h2, nullptr, wf3, b3, g3, be3, out, N);
}